// round 12
// baseline (speedup 1.0000x reference)
#include <cuda_runtime.h>
#include <cuda_fp16.h>
#include <cstdint>

// ---------------- problem constants ----------------
static constexpr int BS    = 32;
static constexpr int RB    = 128;   // row blocks
static constexpr int CBLK  = 128;   // col blocks
static constexpr int PAIRS = 7;     // ceil(13/2) col-block pairs (padded)
static constexpr int SLOTS = 14;    // padded nnz slots per row
static constexpr int NCOL  = CBLK * BS;   // 4096
static constexpr int MAXBATCH = 2048;
static constexpr int MT    = 128;   // batch rows per CTA
static constexpr int TPB   = 128;   // 4 warps; warp w owns rows [32w, 32w+32)

// ---------------- device scratch (static, no allocation) ----------------
// x in mma A-fragment order: per (mtile=row/16, cblk) a 1KB tile:
//   [khalf(2)][lane(32)] x uint4; lane's uint4 = {a0,a1,a2,a3}
__device__ __align__(16) uint4 g_xf[(size_t)(MAXBATCH / 16) * CBLK * 64];   // 16 MB
// B in mma-fragment order: per (rblk,pair) 4KB tile: [ks(4)][h(2)][lane(32)] x uint4
__device__ __align__(16) uint4 g_wpk[(size_t)RB * PAIRS * 256];             // 3.5 MB
__device__ int g_pcols[RB * SLOTS];

// ---------------- PTX helpers ----------------
__device__ __forceinline__ uint32_t smem_u32(const void* p) {
    uint32_t a;
    asm("{ .reg .u64 t; cvta.to.shared.u64 t, %1; cvt.u32.u64 %0, t; }" : "=r"(a) : "l"(p));
    return a;
}
__device__ __forceinline__ void cp_async16(uint32_t dst, const void* src) {
    asm volatile("cp.async.cg.shared.global [%0], [%1], 16;" :: "r"(dst), "l"(src));
}
__device__ __forceinline__ void cp_commit() {
    asm volatile("cp.async.commit_group;" ::: "memory");
}
template <int N>
__device__ __forceinline__ void cp_wait() {
    asm volatile("cp.async.wait_group %0;" :: "n"(N) : "memory");
}
__device__ __forceinline__ void lds128(uint4& v, uint32_t addr) {
    asm volatile("ld.shared.v4.u32 {%0,%1,%2,%3}, [%4];"
                 : "=r"(v.x), "=r"(v.y), "=r"(v.z), "=r"(v.w) : "r"(addr));
}

// ---------------- fused prep kernel (verified R9/R11) ----------------
__global__ void k_prep(const float* __restrict__ x,
                       const int* __restrict__ crow, const int* __restrict__ cols,
                       const float* __restrict__ mask, const float* __restrict__ w,
                       int nconv) {
    int blk = blockIdx.x;
    if (blk < nconv) {
        int uid  = blk * 8 + (threadIdx.x >> 5);
        int lane = threadIdx.x & 31;
        int h    = uid & 1;
        int tile = uid >> 1;                 // mtile*128 + cblk
        int mtile = tile >> 7, cblk = tile & 127;
        int R = mtile * 16, C = cblk * 32 + h * 16;
        int g = lane >> 2, t = lane & 3;

        const float* xr = x + (size_t)(R + g) * NCOL + C + 2 * t;
        float2 f0 = *reinterpret_cast<const float2*>(xr);
        float2 f1 = *reinterpret_cast<const float2*>(xr + 8 * (size_t)NCOL);
        float2 f2 = *reinterpret_cast<const float2*>(xr + 8);
        float2 f3 = *reinterpret_cast<const float2*>(xr + 8 * (size_t)NCOL + 8);
        union { __half2 h2[4]; uint4 v; } u;
        u.h2[0] = __floats2half2_rn(f0.x, f0.y);
        u.h2[1] = __floats2half2_rn(f1.x, f1.y);
        u.h2[2] = __floats2half2_rn(f2.x, f2.y);
        u.h2[3] = __floats2half2_rn(f3.x, f3.y);
        g_xf[(size_t)tile * 64 + h * 32 + lane] = u.v;
    } else if (blk < nconv + RB * PAIRS) {
        int tile = blk - nconv;            // rblk*PAIRS + p
        int rblk = tile / PAIRS, p = tile % PAIRS;
        int q = threadIdx.x;
        int lane = q & 31, idx = q >> 5;
        int ks = idx >> 1, h = idx & 1;
        int n0 = h * 16 + (lane >> 2);
        int kb = ks * 16 + (lane & 3) * 2;
        int beg = crow[rblk];
        int len = crow[rblk + 1] - beg;

        union { __half hv[8]; uint4 v; } u;
#pragma unroll
        for (int r = 0; r < 4; r++) {
            int n = n0 + (r >> 1) * 8;
            int k = kb + (r & 1) * 8;
#pragma unroll
            for (int e = 0; e < 2; e++) {
                int kk = k + e;
                int slot = 2 * p + (kk >> 5);
                float f = 0.0f;
                if (slot < len) {
                    long el = (long)(beg + slot) * 1024 + n * 32 + (kk & 31);
                    f = mask[el] * w[el];
                }
                u.hv[r * 2 + e] = __float2half_rn(f);
            }
        }
        g_wpk[(size_t)tile * 256 + q] = u.v;
    } else {
        for (int i = threadIdx.x; i < RB * SLOTS; i += blockDim.x) {
            int r = i / SLOTS, s = i % SLOTS;
            int beg = crow[r];
            int len = crow[r + 1] - beg;
            g_pcols[i] = (s < len) ? cols[beg + s] : cols[beg + len - 1];
        }
    }
}

// ---------------- main kernel ----------------
// A fragments for one stage: 8 coalesced LDG.128 into registers.
__device__ __forceinline__ void load_a(uint4 a[2][4], const uint4* __restrict__ xf,
                                       int c0, int c1, int lane) {
#pragma unroll
    for (int mi = 0; mi < 2; mi++) {
        const uint4* base = xf + (size_t)mi * CBLK * 64;
        a[mi][0] = __ldg(base + (size_t)c0 * 64 + lane);
        a[mi][1] = __ldg(base + (size_t)c0 * 64 + 32 + lane);
        a[mi][2] = __ldg(base + (size_t)c1 * 64 + lane);
        a[mi][3] = __ldg(base + (size_t)c1 * 64 + 32 + lane);
    }
}

__global__ void __launch_bounds__(TPB, 4)
k_main(const float* __restrict__ bias, float* __restrict__ out) {
    __shared__ __align__(16) uint4 sB[PAIRS * 256];   // 28 KB: all B tiles
    int tid = threadIdx.x;
    int wid = tid >> 5, lane = tid & 31;
    int mt = blockIdx.x;       // batch tile of MT rows
    int rblk = blockIdx.y;     // row block

    const int* pc = g_pcols + rblk * SLOTS;
    const uint4* xf = g_xf + ((size_t)mt * 8 + wid * 2) * CBLK * 64;

    // Stage B tiles: stage-0 tile first (own group), then tiles 1-6.
    uint32_t sbB = smem_u32(sB);
    {
        const uint4* wt = g_wpk + (size_t)rblk * PAIRS * 256;
#pragma unroll
        for (int t = tid; t < 256; t += TPB)
            cp_async16(sbB + t * 16, wt + t);
        cp_commit();
#pragma unroll
        for (int t = 256 + tid; t < PAIRS * 256; t += TPB)
            cp_async16(sbB + t * 16, wt + t);
        cp_commit();
    }

    // A triple-buffer in registers; prime stages 0 and 1 (overlaps B staging).
    uint4 a[3][2][4];
    load_a(a[0], xf, __ldg(pc + 0), __ldg(pc + 1), lane);
    load_a(a[1], xf, __ldg(pc + 2), __ldg(pc + 3), lane);

    float acc[2][4][4];
#pragma unroll
    for (int m = 0; m < 2; m++)
#pragma unroll
        for (int i = 0; i < 4; i++)
#pragma unroll
            for (int j = 0; j < 4; j++) acc[m][i][j] = 0.0f;

    // Only stage-0's B tile must be resident to start.
    cp_wait<1>();
    __syncthreads();

#pragma unroll
    for (int p = 0; p < PAIRS; p++) {
        // Prefetch A two stages ahead (covers full L2 latency).
        if (p + 2 < PAIRS)
            load_a(a[(p + 2) % 3], xf, __ldg(pc + 2 * p + 4), __ldg(pc + 2 * p + 5), lane);

        if (p == 1) {   // tiles 1-6 must now be resident
            cp_wait<0>();
            __syncthreads();
        }

        uint32_t bbase = sbB + p * 4096 + lane * 16;
#pragma unroll
        for (int ks = 0; ks < 4; ks++) {
            uint4 b0, b1;
            lds128(b0, bbase + (ks * 2 + 0) * 512);
            lds128(b1, bbase + (ks * 2 + 1) * 512);
#pragma unroll
            for (int mi = 0; mi < 2; mi++) {
                const uint4& av = a[p % 3][mi][ks];
#pragma unroll
                for (int nt = 0; nt < 4; nt++) {
                    const uint4& bb = (nt >> 1) ? b1 : b0;
                    uint32_t r0 = (nt & 1) ? bb.z : bb.x;
                    uint32_t r1 = (nt & 1) ? bb.w : bb.y;
                    asm volatile(
                        "mma.sync.aligned.m16n8k16.row.col.f32.f16.f16.f32 "
                        "{%0,%1,%2,%3}, {%4,%5,%6,%7}, {%8,%9}, {%0,%1,%2,%3};"
                        : "+f"(acc[mi][nt][0]), "+f"(acc[mi][nt][1]),
                          "+f"(acc[mi][nt][2]), "+f"(acc[mi][nt][3])
                        : "r"(av.x), "r"(av.y), "r"(av.z), "r"(av.w),
                          "r"(r0), "r"(r1));
                }
            }
        }
    }

    // Epilogue: warp-private rows; + bias.
    int grp = lane >> 2, qid = lane & 3;
    const float* bbp = bias + rblk * BS;
#pragma unroll
    for (int mi = 0; mi < 2; mi++) {
        int row0 = mt * MT + wid * 32 + mi * 16 + grp;
        float* obase = out + (size_t)row0 * NCOL + rblk * BS;
#pragma unroll
        for (int nt = 0; nt < 4; nt++) {
            int col = nt * 8 + 2 * qid;
            float2 bv = *reinterpret_cast<const float2*>(bbp + col);
            float2 v0 = make_float2(acc[mi][nt][0] + bv.x, acc[mi][nt][1] + bv.y);
            float2 v1 = make_float2(acc[mi][nt][2] + bv.x, acc[mi][nt][3] + bv.y);
            *reinterpret_cast<float2*>(obase + col) = v0;
            *reinterpret_cast<float2*>(obase + 8 * (size_t)NCOL + col) = v1;
        }
    }
}

// ---------------- launch ----------------
extern "C" void kernel_launch(void* const* d_in, const int* in_sizes, int n_in,
                              void* d_out, int out_size) {
    const float* x      = (const float*)d_in[0];
    const int*   crow   = (const int*)d_in[1];
    const int*   cols   = (const int*)d_in[2];
    const float* mask   = (const float*)d_in[3];
    const float* weight = (const float*)d_in[4];
    const float* bias   = (const float*)d_in[5];
    float* out = (float*)d_out;

    int batch = in_sizes[0] / NCOL;   // 2048
    int nconv = batch * 2;            // convert blocks (8 warp-units each)

    k_prep<<<nconv + RB * PAIRS + 1, 256>>>(x, crow, cols, mask, weight, nconv);

    dim3 grid(batch / MT, RB);
    k_main<<<grid, TPB>>>(bias, out);
}

// round 13
// speedup vs baseline: 1.0362x; 1.0362x over previous
#include <cuda_runtime.h>
#include <cuda_fp16.h>
#include <cstdint>

// ---------------- problem constants ----------------
static constexpr int BS    = 32;
static constexpr int RB    = 128;   // row blocks
static constexpr int CBLK  = 128;   // col blocks
static constexpr int PAIRS = 7;     // ceil(13/2) col-block pairs (padded)
static constexpr int SLOTS = 14;    // padded nnz slots per row
static constexpr int NCOL  = CBLK * BS;   // 4096
static constexpr int MAXBATCH = 2048;
static constexpr int MT    = 128;   // batch rows per CTA
static constexpr int TPB   = 128;   // 4 warps; warp w owns rows [32w, 32w+32)

// ---------------- device scratch (static, no allocation) ----------------
// x in mma A-fragment order: per (mtile=row/16, cblk) a 1KB tile:
//   [khalf(2)][lane(32)] x uint4; lane's uint4 = {a0,a1,a2,a3}
__device__ __align__(16) uint4 g_xf[(size_t)(MAXBATCH / 16) * CBLK * 64];   // 16 MB
// B in mma-fragment order: per (rblk,pair) 4KB tile: [ks(4)][h(2)][lane(32)] x uint4
__device__ __align__(16) uint4 g_wpk[(size_t)RB * PAIRS * 256];             // 3.5 MB
__device__ int g_pcols[RB * SLOTS];

// ---------------- PTX helpers ----------------
__device__ __forceinline__ uint32_t smem_u32(const void* p) {
    uint32_t a;
    asm("{ .reg .u64 t; cvta.to.shared.u64 t, %1; cvt.u32.u64 %0, t; }" : "=r"(a) : "l"(p));
    return a;
}
__device__ __forceinline__ void cp_async16(uint32_t dst, const void* src) {
    asm volatile("cp.async.cg.shared.global [%0], [%1], 16;" :: "r"(dst), "l"(src));
}
__device__ __forceinline__ void cp_commit() {
    asm volatile("cp.async.commit_group;" ::: "memory");
}
template <int N>
__device__ __forceinline__ void cp_wait() {
    asm volatile("cp.async.wait_group %0;" :: "n"(N) : "memory");
}
__device__ __forceinline__ void lds128(uint4& v, uint32_t addr) {
    asm volatile("ld.shared.v4.u32 {%0,%1,%2,%3}, [%4];"
                 : "=r"(v.x), "=r"(v.y), "=r"(v.z), "=r"(v.w) : "r"(addr));
}

// ---------------- fused prep kernel ----------------
// Blocks [0, nconv): fragment-shuffle x (8 warp-units per block).
// Blocks [nconv, nconv+RB*PAIRS): pack weights via coalesced smem bounce.
// Block nconv+RB*PAIRS: pad col table.
__global__ void k_prep(const float* __restrict__ x,
                       const int* __restrict__ crow, const int* __restrict__ cols,
                       const float* __restrict__ mask, const float* __restrict__ w,
                       int nconv) {
    __shared__ __half sw[2][32][32];   // [slot][n][k] masked fp16 weights (4 KB)
    int blk = blockIdx.x;
    if (blk < nconv) {
        // ---- convert x -> g_xf (fragment order; sector-efficient, verified R7+) ----
        int uid  = blk * 8 + (threadIdx.x >> 5);
        int lane = threadIdx.x & 31;
        int h    = uid & 1;
        int tile = uid >> 1;                 // mtile*128 + cblk
        int mtile = tile >> 7, cblk = tile & 127;
        int R = mtile * 16, C = cblk * 32 + h * 16;
        int g = lane >> 2, t = lane & 3;

        const float* xr = x + (size_t)(R + g) * NCOL + C + 2 * t;
        float2 f0 = *reinterpret_cast<const float2*>(xr);
        float2 f1 = *reinterpret_cast<const float2*>(xr + 8 * (size_t)NCOL);
        float2 f2 = *reinterpret_cast<const float2*>(xr + 8);
        float2 f3 = *reinterpret_cast<const float2*>(xr + 8 * (size_t)NCOL + 8);
        union { __half2 h2[4]; uint4 v; } u;
        u.h2[0] = __floats2half2_rn(f0.x, f0.y);
        u.h2[1] = __floats2half2_rn(f1.x, f1.y);
        u.h2[2] = __floats2half2_rn(f2.x, f2.y);
        u.h2[3] = __floats2half2_rn(f3.x, f3.y);
        g_xf[(size_t)tile * 64 + h * 32 + lane] = u.v;
    } else if (blk < nconv + RB * PAIRS) {
        // ---- pack masked fp16 weights in B-fragment order, coalesced reads ----
        int tile = blk - nconv;            // rblk*PAIRS + p
        int rblk = tile / PAIRS, p = tile % PAIRS;
        int q = threadIdx.x;
        int beg = crow[rblk];
        int len = crow[rblk + 1] - beg;

        // Phase 1: coalesced float4 loads of the pair's two 32x32 blocks -> smem.
#pragma unroll
        for (int s = 0; s < 2; s++) {
            int slot = 2 * p + s;
            float4 wv = make_float4(0.f, 0.f, 0.f, 0.f);
            if (slot < len) {
                const float4* wp = reinterpret_cast<const float4*>(w    + (size_t)(beg + slot) * 1024);
                const float4* mp = reinterpret_cast<const float4*>(mask + (size_t)(beg + slot) * 1024);
                float4 a = wp[q], m = mp[q];
                wv = make_float4(a.x * m.x, a.y * m.y, a.z * m.z, a.w * m.w);
            }
            int n = q >> 3;            // (q*4)/32
            int k = (q & 7) * 4;
            sw[s][n][k + 0] = __float2half_rn(wv.x);
            sw[s][n][k + 1] = __float2half_rn(wv.y);
            sw[s][n][k + 2] = __float2half_rn(wv.z);
            sw[s][n][k + 3] = __float2half_rn(wv.w);
        }
        __syncthreads();

        // Phase 2: gather this thread's fragment from smem; coalesced write.
        int lane = q & 31, idx = q >> 5;
        int ks = idx >> 1, h = idx & 1;
        int n0 = h * 16 + (lane >> 2);
        int kb = ks * 16 + (lane & 3) * 2;
        union { __half hv[8]; uint4 v; } u;
#pragma unroll
        for (int r = 0; r < 4; r++) {
            int n = n0 + (r >> 1) * 8;
            int k = kb + (r & 1) * 8;
#pragma unroll
            for (int e = 0; e < 2; e++) {
                int kk = k + e;
                u.hv[r * 2 + e] = sw[kk >> 5][n][kk & 31];
            }
        }
        g_wpk[(size_t)tile * 256 + q] = u.v;
    } else {
        // ---- pad col table with last valid col (B half is zero there) ----
        for (int i = threadIdx.x; i < RB * SLOTS; i += blockDim.x) {
            int r = i / SLOTS, s = i % SLOTS;
            int beg = crow[r];
            int len = crow[r + 1] - beg;
            g_pcols[i] = (s < len) ? cols[beg + s] : cols[beg + len - 1];
        }
    }
}

// ---------------- main kernel (R11/R12 verified best: 26.5us) ----------------
// A fragments for one stage: 8 coalesced LDG.128 into registers.
__device__ __forceinline__ void load_a(uint4 a[2][4], const uint4* __restrict__ xf,
                                       int c0, int c1, int lane) {
#pragma unroll
    for (int mi = 0; mi < 2; mi++) {
        const uint4* base = xf + (size_t)mi * CBLK * 64;
        a[mi][0] = __ldg(base + (size_t)c0 * 64 + lane);
        a[mi][1] = __ldg(base + (size_t)c0 * 64 + 32 + lane);
        a[mi][2] = __ldg(base + (size_t)c1 * 64 + lane);
        a[mi][3] = __ldg(base + (size_t)c1 * 64 + 32 + lane);
    }
}

__global__ void __launch_bounds__(TPB, 4)
k_main(const float* __restrict__ bias, float* __restrict__ out) {
    __shared__ __align__(16) uint4 sB[PAIRS * 256];   // 28 KB: all B tiles
    int tid = threadIdx.x;
    int wid = tid >> 5, lane = tid & 31;
    int mt = blockIdx.x;       // batch tile of MT rows
    int rblk = blockIdx.y;     // row block

    const int* pc = g_pcols + rblk * SLOTS;
    const uint4* xf = g_xf + ((size_t)mt * 8 + wid * 2) * CBLK * 64;

    // Stage B tiles: stage-0 tile first (own group), then tiles 1-6.
    uint32_t sbB = smem_u32(sB);
    {
        const uint4* wt = g_wpk + (size_t)rblk * PAIRS * 256;
#pragma unroll
        for (int t = tid; t < 256; t += TPB)
            cp_async16(sbB + t * 16, wt + t);
        cp_commit();
#pragma unroll
        for (int t = 256 + tid; t < PAIRS * 256; t += TPB)
            cp_async16(sbB + t * 16, wt + t);
        cp_commit();
    }

    // A double-buffer in registers; prime stage 0 (overlaps with B staging).
    uint4 a[2][2][4];
    load_a(a[0], xf, __ldg(pc + 0), __ldg(pc + 1), lane);

    float acc[2][4][4];
#pragma unroll
    for (int m = 0; m < 2; m++)
#pragma unroll
        for (int i = 0; i < 4; i++)
#pragma unroll
            for (int j = 0; j < 4; j++) acc[m][i][j] = 0.0f;

    // Only stage-0's B tile must be resident to start.
    cp_wait<1>();
    __syncthreads();

#pragma unroll
    for (int p = 0; p < PAIRS; p++) {
        // Prefetch next stage's A while computing this one.
        if (p + 1 < PAIRS)
            load_a(a[(p + 1) & 1], xf, __ldg(pc + 2 * p + 2), __ldg(pc + 2 * p + 3), lane);

        if (p == 1) {   // tiles 1-6 must now be resident
            cp_wait<0>();
            __syncthreads();
        }

        uint32_t bbase = sbB + p * 4096 + lane * 16;
#pragma unroll
        for (int ks = 0; ks < 4; ks++) {
            uint4 b0, b1;
            lds128(b0, bbase + (ks * 2 + 0) * 512);
            lds128(b1, bbase + (ks * 2 + 1) * 512);
#pragma unroll
            for (int mi = 0; mi < 2; mi++) {
                const uint4& av = a[p & 1][mi][ks];
#pragma unroll
                for (int nt = 0; nt < 4; nt++) {
                    const uint4& bb = (nt >> 1) ? b1 : b0;
                    uint32_t r0 = (nt & 1) ? bb.z : bb.x;
                    uint32_t r1 = (nt & 1) ? bb.w : bb.y;
                    asm volatile(
                        "mma.sync.aligned.m16n8k16.row.col.f32.f16.f16.f32 "
                        "{%0,%1,%2,%3}, {%4,%5,%6,%7}, {%8,%9}, {%0,%1,%2,%3};"
                        : "+f"(acc[mi][nt][0]), "+f"(acc[mi][nt][1]),
                          "+f"(acc[mi][nt][2]), "+f"(acc[mi][nt][3])
                        : "r"(av.x), "r"(av.y), "r"(av.z), "r"(av.w),
                          "r"(r0), "r"(r1));
                }
            }
        }
    }

    // Epilogue: warp-private rows; + bias.
    int grp = lane >> 2, qid = lane & 3;
    const float* bbp = bias + rblk * BS;
#pragma unroll
    for (int mi = 0; mi < 2; mi++) {
        int row0 = mt * MT + wid * 32 + mi * 16 + grp;
        float* obase = out + (size_t)row0 * NCOL + rblk * BS;
#pragma unroll
        for (int nt = 0; nt < 4; nt++) {
            int col = nt * 8 + 2 * qid;
            float2 bv = *reinterpret_cast<const float2*>(bbp + col);
            float2 v0 = make_float2(acc[mi][nt][0] + bv.x, acc[mi][nt][1] + bv.y);
            float2 v1 = make_float2(acc[mi][nt][2] + bv.x, acc[mi][nt][3] + bv.y);
            *reinterpret_cast<float2*>(obase + col) = v0;
            *reinterpret_cast<float2*>(obase + 8 * (size_t)NCOL + col) = v1;
        }
    }
}

// ---------------- launch ----------------
extern "C" void kernel_launch(void* const* d_in, const int* in_sizes, int n_in,
                              void* d_out, int out_size) {
    const float* x      = (const float*)d_in[0];
    const int*   crow   = (const int*)d_in[1];
    const int*   cols   = (const int*)d_in[2];
    const float* mask   = (const float*)d_in[3];
    const float* weight = (const float*)d_in[4];
    const float* bias   = (const float*)d_in[5];
    float* out = (float*)d_out;

    int batch = in_sizes[0] / NCOL;   // 2048
    int nconv = batch * 2;            // convert blocks (8 warp-units each)

    k_prep<<<nconv + RB * PAIRS + 1, 256>>>(x, crow, cols, mask, weight, nconv);

    dim3 grid(batch / MT, RB);
    k_main<<<grid, TPB>>>(bias, out);
}

// round 14
// speedup vs baseline: 1.0557x; 1.0189x over previous
#include <cuda_runtime.h>
#include <cuda_fp16.h>
#include <cstdint>

// ---------------- problem constants ----------------
static constexpr int BS    = 32;
static constexpr int RB    = 128;   // row blocks
static constexpr int CBLK  = 128;   // col blocks
static constexpr int PAIRS = 7;     // ceil(13/2) col-block pairs (padded)
static constexpr int SLOTS = 14;    // padded nnz slots per row
static constexpr int NCOL  = CBLK * BS;   // 4096
static constexpr int MAXBATCH = 2048;
static constexpr int MT    = 256;   // batch rows per CTA
static constexpr int TPB   = 256;   // 8 warps; warp w owns rows [32w, 32w+32)

// ---------------- device scratch (static, no allocation) ----------------
// x in mma A-fragment order: per (mtile=row/16, cblk) a 1KB tile:
//   [khalf(2)][lane(32)] x uint4; lane's uint4 = {a0,a1,a2,a3}
__device__ __align__(16) uint4 g_xf[(size_t)(MAXBATCH / 16) * CBLK * 64];   // 16 MB
// B in mma-fragment order: per (rblk,pair) 4KB tile: [ks(4)][h(2)][lane(32)] x uint4
__device__ __align__(16) uint4 g_wpk[(size_t)RB * PAIRS * 256];             // 3.5 MB
__device__ int g_pcols[RB * SLOTS];

// ---------------- PTX helpers ----------------
__device__ __forceinline__ uint32_t smem_u32(const void* p) {
    uint32_t a;
    asm("{ .reg .u64 t; cvta.to.shared.u64 t, %1; cvt.u32.u64 %0, t; }" : "=r"(a) : "l"(p));
    return a;
}
__device__ __forceinline__ void cp_async16(uint32_t dst, const void* src) {
    asm volatile("cp.async.cg.shared.global [%0], [%1], 16;" :: "r"(dst), "l"(src));
}
__device__ __forceinline__ void cp_commit() {
    asm volatile("cp.async.commit_group;" ::: "memory");
}
template <int N>
__device__ __forceinline__ void cp_wait() {
    asm volatile("cp.async.wait_group %0;" :: "n"(N) : "memory");
}
__device__ __forceinline__ void lds128(uint4& v, uint32_t addr) {
    asm volatile("ld.shared.v4.u32 {%0,%1,%2,%3}, [%4];"
                 : "=r"(v.x), "=r"(v.y), "=r"(v.z), "=r"(v.w) : "r"(addr));
}

// ---------------- fused prep kernel (verified R13) ----------------
__global__ void k_prep(const float* __restrict__ x,
                       const int* __restrict__ crow, const int* __restrict__ cols,
                       const float* __restrict__ mask, const float* __restrict__ w,
                       int nconv) {
    __shared__ __half sw[2][32][32];   // [slot][n][k] masked fp16 weights (4 KB)
    int blk = blockIdx.x;
    if (blk < nconv) {
        int uid  = blk * 8 + (threadIdx.x >> 5);
        int lane = threadIdx.x & 31;
        int h    = uid & 1;
        int tile = uid >> 1;                 // mtile*128 + cblk
        int mtile = tile >> 7, cblk = tile & 127;
        int R = mtile * 16, C = cblk * 32 + h * 16;
        int g = lane >> 2, t = lane & 3;

        const float* xr = x + (size_t)(R + g) * NCOL + C + 2 * t;
        float2 f0 = *reinterpret_cast<const float2*>(xr);
        float2 f1 = *reinterpret_cast<const float2*>(xr + 8 * (size_t)NCOL);
        float2 f2 = *reinterpret_cast<const float2*>(xr + 8);
        float2 f3 = *reinterpret_cast<const float2*>(xr + 8 * (size_t)NCOL + 8);
        union { __half2 h2[4]; uint4 v; } u;
        u.h2[0] = __floats2half2_rn(f0.x, f0.y);
        u.h2[1] = __floats2half2_rn(f1.x, f1.y);
        u.h2[2] = __floats2half2_rn(f2.x, f2.y);
        u.h2[3] = __floats2half2_rn(f3.x, f3.y);
        g_xf[(size_t)tile * 64 + h * 32 + lane] = u.v;
    } else if (blk < nconv + RB * PAIRS) {
        int tile = blk - nconv;            // rblk*PAIRS + p
        int rblk = tile / PAIRS, p = tile % PAIRS;
        int q = threadIdx.x;
        int beg = crow[rblk];
        int len = crow[rblk + 1] - beg;

        // Phase 1: coalesced float4 loads of the pair's two 32x32 blocks -> smem.
#pragma unroll
        for (int s = 0; s < 2; s++) {
            int slot = 2 * p + s;
            float4 wv = make_float4(0.f, 0.f, 0.f, 0.f);
            if (slot < len) {
                const float4* wp = reinterpret_cast<const float4*>(w    + (size_t)(beg + slot) * 1024);
                const float4* mp = reinterpret_cast<const float4*>(mask + (size_t)(beg + slot) * 1024);
                float4 a = wp[q], m = mp[q];
                wv = make_float4(a.x * m.x, a.y * m.y, a.z * m.z, a.w * m.w);
            }
            int n = q >> 3;
            int k = (q & 7) * 4;
            sw[s][n][k + 0] = __float2half_rn(wv.x);
            sw[s][n][k + 1] = __float2half_rn(wv.y);
            sw[s][n][k + 2] = __float2half_rn(wv.z);
            sw[s][n][k + 3] = __float2half_rn(wv.w);
        }
        __syncthreads();

        // Phase 2: gather fragment from smem; coalesced write.
        int lane = q & 31, idx = q >> 5;
        int ks = idx >> 1, h = idx & 1;
        int n0 = h * 16 + (lane >> 2);
        int kb = ks * 16 + (lane & 3) * 2;
        union { __half hv[8]; uint4 v; } u;
#pragma unroll
        for (int r = 0; r < 4; r++) {
            int n = n0 + (r >> 1) * 8;
            int k = kb + (r & 1) * 8;
#pragma unroll
            for (int e = 0; e < 2; e++) {
                int kk = k + e;
                u.hv[r * 2 + e] = sw[kk >> 5][n][kk & 31];
            }
        }
        g_wpk[(size_t)tile * 256 + q] = u.v;
    } else {
        for (int i = threadIdx.x; i < RB * SLOTS; i += blockDim.x) {
            int r = i / SLOTS, s = i % SLOTS;
            int beg = crow[r];
            int len = crow[r + 1] - beg;
            g_pcols[i] = (s < len) ? cols[beg + s] : cols[beg + len - 1];
        }
    }
}

// ---------------- main kernel ----------------
// A fragments for one stage: 8 coalesced LDG.128 into registers.
__device__ __forceinline__ void load_a(uint4 a[2][4], const uint4* __restrict__ xf,
                                       int c0, int c1, int lane) {
#pragma unroll
    for (int mi = 0; mi < 2; mi++) {
        const uint4* base = xf + (size_t)mi * CBLK * 64;
        a[mi][0] = __ldg(base + (size_t)c0 * 64 + lane);
        a[mi][1] = __ldg(base + (size_t)c0 * 64 + 32 + lane);
        a[mi][2] = __ldg(base + (size_t)c1 * 64 + lane);
        a[mi][3] = __ldg(base + (size_t)c1 * 64 + 32 + lane);
    }
}

__global__ void __launch_bounds__(TPB, 2)
k_main(const float* __restrict__ bias, float* __restrict__ out) {
    __shared__ __align__(16) uint4 sB[PAIRS * 256];   // 28 KB: all B tiles
    int tid = threadIdx.x;
    int wid = tid >> 5, lane = tid & 31;
    int mt = blockIdx.x;       // batch tile of MT rows
    int rblk = blockIdx.y;     // row block

    const int* pc = g_pcols + rblk * SLOTS;
    // Warp owns mtiles mt*16 + wid*2 .. +1 (rows mt*256 + wid*32 .. +32)
    const uint4* xf = g_xf + ((size_t)mt * 16 + wid * 2) * CBLK * 64;

    // Stage B tiles: stage-0 tile first (own group), then tiles 1-6.
    uint32_t sbB = smem_u32(sB);
    {
        const uint4* wt = g_wpk + (size_t)rblk * PAIRS * 256;
        cp_async16(sbB + tid * 16, wt + tid);
        cp_commit();
#pragma unroll
        for (int t = 256 + tid; t < PAIRS * 256; t += TPB)
            cp_async16(sbB + t * 16, wt + t);
        cp_commit();
    }

    // A double-buffer in registers; prime stage 0 (overlaps with B staging).
    uint4 a[2][2][4];
    load_a(a[0], xf, __ldg(pc + 0), __ldg(pc + 1), lane);

    float acc[2][4][4];
#pragma unroll
    for (int m = 0; m < 2; m++)
#pragma unroll
        for (int i = 0; i < 4; i++)
#pragma unroll
            for (int j = 0; j < 4; j++) acc[m][i][j] = 0.0f;

    // Only stage-0's B tile must be resident to start.
    cp_wait<1>();
    __syncthreads();

#pragma unroll
    for (int p = 0; p < PAIRS; p++) {
        // Prefetch next stage's A while computing this one.
        if (p + 1 < PAIRS)
            load_a(a[(p + 1) & 1], xf, __ldg(pc + 2 * p + 2), __ldg(pc + 2 * p + 3), lane);

        if (p == 1) {   // tiles 1-6 must now be resident
            cp_wait<0>();
            __syncthreads();
        }

        uint32_t bbase = sbB + p * 4096 + lane * 16;
#pragma unroll
        for (int ks = 0; ks < 4; ks++) {
            uint4 b0, b1;
            lds128(b0, bbase + (ks * 2 + 0) * 512);
            lds128(b1, bbase + (ks * 2 + 1) * 512);
#pragma unroll
            for (int mi = 0; mi < 2; mi++) {
                const uint4& av = a[p & 1][mi][ks];
#pragma unroll
                for (int nt = 0; nt < 4; nt++) {
                    const uint4& bb = (nt >> 1) ? b1 : b0;
                    uint32_t r0 = (nt & 1) ? bb.z : bb.x;
                    uint32_t r1 = (nt & 1) ? bb.w : bb.y;
                    asm volatile(
                        "mma.sync.aligned.m16n8k16.row.col.f32.f16.f16.f32 "
                        "{%0,%1,%2,%3}, {%4,%5,%6,%7}, {%8,%9}, {%0,%1,%2,%3};"
                        : "+f"(acc[mi][nt][0]), "+f"(acc[mi][nt][1]),
                          "+f"(acc[mi][nt][2]), "+f"(acc[mi][nt][3])
                        : "r"(av.x), "r"(av.y), "r"(av.z), "r"(av.w),
                          "r"(r0), "r"(r1));
                }
            }
        }
    }

    // Epilogue: warp-private rows; + bias.
    int grp = lane >> 2, qid = lane & 3;
    const float* bbp = bias + rblk * BS;
#pragma unroll
    for (int mi = 0; mi < 2; mi++) {
        int row0 = mt * MT + wid * 32 + mi * 16 + grp;
        float* obase = out + (size_t)row0 * NCOL + rblk * BS;
#pragma unroll
        for (int nt = 0; nt < 4; nt++) {
            int col = nt * 8 + 2 * qid;
            float2 bv = *reinterpret_cast<const float2*>(bbp + col);
            float2 v0 = make_float2(acc[mi][nt][0] + bv.x, acc[mi][nt][1] + bv.y);
            float2 v1 = make_float2(acc[mi][nt][2] + bv.x, acc[mi][nt][3] + bv.y);
            *reinterpret_cast<float2*>(obase + col) = v0;
            *reinterpret_cast<float2*>(obase + 8 * (size_t)NCOL + col) = v1;
        }
    }
}

// ---------------- launch ----------------
extern "C" void kernel_launch(void* const* d_in, const int* in_sizes, int n_in,
                              void* d_out, int out_size) {
    const float* x      = (const float*)d_in[0];
    const int*   crow   = (const int*)d_in[1];
    const int*   cols   = (const int*)d_in[2];
    const float* mask   = (const float*)d_in[3];
    const float* weight = (const float*)d_in[4];
    const float* bias   = (const float*)d_in[5];
    float* out = (float*)d_out;

    int batch = in_sizes[0] / NCOL;   // 2048
    int nconv = batch * 2;            // convert blocks (8 warp-units each)

    k_prep<<<nconv + RB * PAIRS + 1, 256>>>(x, crow, cols, mask, weight, nconv);

    dim3 grid(batch / MT, RB);
    k_main<<<grid, TPB>>>(bias, out);
}